// round 14
// baseline (speedup 1.0000x reference)
#include <cuda_runtime.h>
#include <cuda_bf16.h>
#include <cuda_fp16.h>
#include <math.h>

#define S_LEN  4096
#define HDIM   2048
#define NHQ    8
#define NKV    2
#define DH     256
#define WINDOW 512
#define NQKV   3072

// fp32 scratch: merged QKV projection output [S][3072]
__device__ float g_qkv[S_LEN * NQKV];

// int8 quant operands for QKV GEMM
__device__ signed char g_ha0[S_LEN * HDIM];       // hs limb0
__device__ signed char g_ha1[S_LEN * HDIM];       // hs limb1
__device__ signed char g_wq0[NQKV * HDIM];        // merged weights limb0 [n][k]
__device__ signed char g_wq1[NQKV * HDIM];        // merged weights limb1 [n][k]
__device__ float g_sa[S_LEN];                     // per-row scale of hs
__device__ float g_sb[NQKV];                      // per-outcol scale of merged W

// bf16/fp16 scratch (R12 attention + O-proj path)
__device__ __nv_bfloat16 g_a0[S_LEN * HDIM];      // q bf16 hi
__device__ __nv_bfloat16 g_a1[S_LEN * HDIM];      // q bf16 lo
__device__ __nv_bfloat16 g_o0[S_LEN * HDIM];      // attention output splits
__device__ __nv_bfloat16 g_o1[S_LEN * HDIM];
__device__ __nv_bfloat16 g_wo0[HDIM * HDIM];
__device__ __nv_bfloat16 g_wo1[HDIM * HDIM];
__device__ __nv_bfloat16 g_k0s[S_LEN * NKV * DH];
__device__ __nv_bfloat16 g_k1s[S_LEN * NKV * DH];
__device__ __half        g_vt[NKV * DH * S_LEN];  // v fp16 [h][d][s]

// ===========================================================================
// Helpers
// ===========================================================================
__device__ __forceinline__ unsigned smem_u32(const void* p) {
    unsigned a;
    asm("{ .reg .u64 t; cvta.to.shared.u64 t, %1; cvt.u32.u64 %0, t; }"
        : "=r"(a) : "l"(p));
    return a;
}

#define CP_ASYNC16(dst, src) \
    asm volatile("cp.async.cg.shared.global [%0], [%1], 16;" :: "r"(dst), "l"(src) : "memory")
#define CP_COMMIT() asm volatile("cp.async.commit_group;" ::: "memory")

__device__ __forceinline__ void bf16_split(float x, __nv_bfloat16& h, __nv_bfloat16& l) {
    h = __float2bfloat16_rn(x);
    l = __float2bfloat16_rn(x - __bfloat162float(h));
}

__device__ __forceinline__ unsigned hpack2(float x, float y) {
    __half2 p = __floats2half2_rn(x, y);
    return *(unsigned*)&p;
}

__device__ __forceinline__ void mma_bf16(float* d, const unsigned* a, const unsigned* b) {
    asm volatile(
        "mma.sync.aligned.m16n8k16.row.col.f32.bf16.bf16.f32 "
        "{%0,%1,%2,%3}, {%4,%5,%6,%7}, {%8,%9}, {%0,%1,%2,%3};"
        : "+f"(d[0]), "+f"(d[1]), "+f"(d[2]), "+f"(d[3])
        : "r"(a[0]), "r"(a[1]), "r"(a[2]), "r"(a[3]), "r"(b[0]), "r"(b[1]));
}

__device__ __forceinline__ void mma_f16(float* d, const unsigned* a, const unsigned* b) {
    asm volatile(
        "mma.sync.aligned.m16n8k16.row.col.f32.f16.f16.f32 "
        "{%0,%1,%2,%3}, {%4,%5,%6,%7}, {%8,%9}, {%0,%1,%2,%3};"
        : "+f"(d[0]), "+f"(d[1]), "+f"(d[2]), "+f"(d[3])
        : "r"(a[0]), "r"(a[1]), "r"(a[2]), "r"(a[3]), "r"(b[0]), "r"(b[1]));
}

__device__ __forceinline__ void mma_s8(int* d, const unsigned* a, const unsigned* b) {
    asm volatile(
        "mma.sync.aligned.m16n8k32.row.col.s32.s8.s8.s32 "
        "{%0,%1,%2,%3}, {%4,%5,%6,%7}, {%8,%9}, {%0,%1,%2,%3};"
        : "+r"(d[0]), "+r"(d[1]), "+r"(d[2]), "+r"(d[3])
        : "r"(a[0]), "r"(a[1]), "r"(a[2]), "r"(a[3]), "r"(b[0]), "r"(b[1]));
}

// ===========================================================================
// Row quantize: fp32 [M][K] -> int8 limbs [M][K] x2 + per-row scale.
// One block per row, 256 threads, float4/char4 vectorized.
// ===========================================================================
__global__ __launch_bounds__(256) void quant_rows_kernel(
    const float* __restrict__ in, signed char* __restrict__ q0,
    signed char* __restrict__ q1, float* __restrict__ scale, int K)
{
    const int r = blockIdx.x;
    const float* row = in + (size_t)r * K;
    float mx = 0.f;
    for (int i = threadIdx.x * 4; i < K; i += 1024) {
        float4 v = *(const float4*)(row + i);
        mx = fmaxf(mx, fmaxf(fmaxf(fabsf(v.x), fabsf(v.y)),
                             fmaxf(fabsf(v.z), fabsf(v.w))));
    }
#pragma unroll
    for (int o = 16; o > 0; o >>= 1) mx = fmaxf(mx, __shfl_xor_sync(0xffffffffu, mx, o));
    __shared__ float red[8];
    __shared__ float sS;
    if ((threadIdx.x & 31) == 0) red[threadIdx.x >> 5] = mx;
    __syncthreads();
    if (threadIdx.x == 0) {
        float m = red[0];
#pragma unroll
        for (int i = 1; i < 8; i++) m = fmaxf(m, red[i]);
        sS = m;
        scale[r] = m;
    }
    __syncthreads();
    const float s = sS;
    const float inv = (s > 0.f) ? 127.f / s : 0.f;
    for (int i = threadIdx.x * 4; i < K; i += 1024) {
        float4 v = *(const float4*)(row + i);
        float q[4] = {v.x * inv, v.y * inv, v.z * inv, v.w * inv};
        char4 c0, c1;
        int A;
        A = __float2int_rn(q[0]); c0.x = (signed char)A; c1.x = (signed char)__float2int_rn((q[0] - A) * 128.f);
        A = __float2int_rn(q[1]); c0.y = (signed char)A; c1.y = (signed char)__float2int_rn((q[1] - A) * 128.f);
        A = __float2int_rn(q[2]); c0.z = (signed char)A; c1.z = (signed char)__float2int_rn((q[2] - A) * 128.f);
        A = __float2int_rn(q[3]); c0.w = (signed char)A; c1.w = (signed char)__float2int_rn((q[3] - A) * 128.f);
        *(char4*)(q0 + (size_t)r * K + i) = c0;
        *(char4*)(q1 + (size_t)r * K + i) = c1;
    }
}

// ===========================================================================
// Column max: W [K][N] -> sB[n] = max_k |W[k][n]|
// ===========================================================================
__global__ __launch_bounds__(256) void colmax_kernel(
    const float* __restrict__ W, float* __restrict__ sB, int K, int N)
{
    int n = blockIdx.x * 256 + threadIdx.x;
    if (n >= N) return;
    float m = 0.f;
    for (int k = 0; k < K; k++) m = fmaxf(m, fabsf(W[(size_t)k * N + n]));
    sB[n] = m;
}

// ===========================================================================
// Transpose-quantize: fp32 W [K][N] -> int8 limbs [N][K] x2 using sB[n].
// ===========================================================================
__global__ __launch_bounds__(256) void tquant_kernel(
    const float* __restrict__ in, signed char* __restrict__ o0,
    signed char* __restrict__ o1, const float* __restrict__ sB, int K, int N)
{
    __shared__ float tile[32][33];
    const int n0 = blockIdx.x * 32;
    const int k0 = blockIdx.y * 32;
    const int tx = threadIdx.x, ty = threadIdx.y;
#pragma unroll
    for (int j = 0; j < 4; j++)
        tile[ty + 8 * j][tx] = in[(size_t)(k0 + ty + 8 * j) * N + n0 + tx];
    __syncthreads();
#pragma unroll
    for (int j = 0; j < 4; j++) {
        int ny = ty + 8 * j;
        float s = sB[n0 + ny];
        float inv = (s > 0.f) ? 127.f / s : 0.f;
        float q = tile[tx][ny] * inv;
        int A0 = __float2int_rn(q);
        int A1 = __float2int_rn((q - (float)A0) * 128.f);
        size_t off = (size_t)(n0 + ny) * K + k0 + tx;
        o0[off] = (signed char)A0;
        o1[off] = (signed char)A1;
    }
}

// ===========================================================================
// Transpose-split to bf16 hi/lo (for w_o): fp32 [K][N] -> bf16 [N][K] x2.
// ===========================================================================
__global__ __launch_bounds__(256) void tsplit_kernel(
    const float* __restrict__ in, __nv_bfloat16* __restrict__ o0,
    __nv_bfloat16* __restrict__ o1, int K, int N)
{
    __shared__ float tile[32][33];
    const int n0 = blockIdx.x * 32;
    const int k0 = blockIdx.y * 32;
    const int tx = threadIdx.x, ty = threadIdx.y;
#pragma unroll
    for (int j = 0; j < 4; j++)
        tile[ty + 8 * j][tx] = in[(size_t)(k0 + ty + 8 * j) * N + n0 + tx];
    __syncthreads();
#pragma unroll
    for (int j = 0; j < 4; j++) {
        int ny = ty + 8 * j;
        float x = tile[tx][ny];
        __nv_bfloat16 h, l;
        bf16_split(x, h, l);
        size_t off = (size_t)(n0 + ny) * K + k0 + tx;
        o0[off] = h;
        o1[off] = l;
    }
}

// ===========================================================================
// V transpose: g_qkv [S][3072] (v at col 2560+) -> fp16 vt [h][DH][S].
// ===========================================================================
__global__ __launch_bounds__(256) void vsplit_t_kernel(
    const float* __restrict__ in, __half* __restrict__ o0)
{
    __shared__ float tile[32][33];
    const int s0 = blockIdx.x * 32;
    const int d0 = blockIdx.y * 32;
    const int hh = blockIdx.z;
    const int tx = threadIdx.x, ty = threadIdx.y;
#pragma unroll
    for (int j = 0; j < 4; j++)
        tile[ty + 8 * j][tx] =
            in[(size_t)(s0 + ty + 8 * j) * NQKV + 2560 + hh * DH + d0 + tx];
    __syncthreads();
#pragma unroll
    for (int j = 0; j < 4; j++) {
        int dy = ty + 8 * j;
        o0[(size_t)(hh * DH + d0 + dy) * S_LEN + s0 + tx] =
            __float2half_rn(tile[tx][dy]);
    }
}

// ===========================================================================
// int8 Ozaki GEMM (QKV): C = sA sB /127^2 * [(A0+A1/128)(B0+B1/128) - A1B1 term]
// mma.m16n8k32.s8: main = A0B0 (persistent s32), cross = A0B1+A1B0 folded
// per chunk as (crs+64)>>7. BM=128, BN=128, BK=32, 256 threads.
// SMEM rows: 32 data bytes + 16 pad = 48 B (stride 12 words, conflict-free).
// ===========================================================================
#define ROW8_B   48
#define ARR8_B   (128 * ROW8_B)              // 6144
#define STAGE8_B (4 * ARR8_B)                // 24576
#define I8STAGES 2
#define I8GEMM_SMEM (I8STAGES * STAGE8_B)    // 49152

__global__ __launch_bounds__(256) void i8_gemm_kernel(
    const signed char* __restrict__ A0, const signed char* __restrict__ A1,
    const signed char* __restrict__ B0, const signed char* __restrict__ B1,
    const float* __restrict__ sA, const float* __restrict__ sB,
    float* __restrict__ C, int M, int N, int K)
{
    extern __shared__ char gsm[];
    const unsigned sbase = smem_u32(gsm);

    const int tid  = threadIdx.x;
    const int wid  = tid >> 5;
    const int lane = tid & 31;
    const int g    = lane >> 2;
    const int t4   = lane & 3;
    const int wm   = wid & 3;
    const int wn   = wid >> 2;

    const int brow = blockIdx.y * 128;
    const int bcol = blockIdx.x * 128;
    const int nchunks = K / 32;

    int acc[2][8][4];
#pragma unroll
    for (int mf = 0; mf < 2; mf++)
#pragma unroll
        for (int nf = 0; nf < 8; nf++)
#pragma unroll
            for (int r = 0; r < 4; r++) acc[mf][nf][r] = 0;

    const signed char* srcs[4] = {A0, A1, B0, B1};

    auto fill_stage = [&](int c, int s) {
        const int k0 = c * 32;
        const unsigned st = sbase + s * STAGE8_B;
#pragma unroll
        for (int j = 0; j < 4; j++) {
            int idx = tid + j * 256;            // 0..1023
            int arr = idx >> 8;                 // 0..3
            int t   = idx & 255;
            int r   = t >> 1, u = t & 1;        // row, 16B unit (2 per row)
            int grow = (arr < 2) ? (brow + r) : (bcol + r);
            const signed char* src = srcs[arr] + (size_t)grow * K + k0 + u * 16;
            CP_ASYNC16(st + (unsigned)(arr * ARR8_B + r * ROW8_B + u * 16), src);
        }
        CP_COMMIT();
    };

#pragma unroll
    for (int c = 0; c < I8STAGES; c++) fill_stage(c, c);

#pragma unroll 1
    for (int c = 0; c < nchunks; c++) {
        const int s = c & 1;
        const int rem = nchunks - 1 - c;
        if (rem >= 1) asm volatile("cp.async.wait_group 1;" ::: "memory");
        else          asm volatile("cp.async.wait_group 0;" ::: "memory");
        __syncthreads();

        const unsigned* sA0w = (const unsigned*)(gsm + s * STAGE8_B);
        const unsigned* sA1w = (const unsigned*)(gsm + s * STAGE8_B + ARR8_B);
        const unsigned* sB0w = (const unsigned*)(gsm + s * STAGE8_B + 2 * ARR8_B);
        const unsigned* sB1w = (const unsigned*)(gsm + s * STAGE8_B + 3 * ARR8_B);
        const int ROW_W = ROW8_B / 4;   // 12 words per row

        unsigned a0f[2][4], a1f[2][4];
#pragma unroll
        for (int mf = 0; mf < 2; mf++) {
            const int r0 = wm * 32 + mf * 16 + g;
            a0f[mf][0] = sA0w[r0 * ROW_W + t4];
            a0f[mf][1] = sA0w[(r0 + 8) * ROW_W + t4];
            a0f[mf][2] = sA0w[r0 * ROW_W + 4 + t4];
            a0f[mf][3] = sA0w[(r0 + 8) * ROW_W + 4 + t4];
            a1f[mf][0] = sA1w[r0 * ROW_W + t4];
            a1f[mf][1] = sA1w[(r0 + 8) * ROW_W + t4];
            a1f[mf][2] = sA1w[r0 * ROW_W + 4 + t4];
            a1f[mf][3] = sA1w[(r0 + 8) * ROW_W + 4 + t4];
        }
#pragma unroll
        for (int nf = 0; nf < 8; nf++) {
            const int n = wn * 64 + nf * 8 + g;
            unsigned b0f[2], b1f[2];
            b0f[0] = sB0w[n * ROW_W + t4];
            b0f[1] = sB0w[n * ROW_W + 4 + t4];
            b1f[0] = sB1w[n * ROW_W + t4];
            b1f[1] = sB1w[n * ROW_W + 4 + t4];
#pragma unroll
            for (int mf = 0; mf < 2; mf++) {
                mma_s8(acc[mf][nf], a0f[mf], b0f);
                int crs[4] = {0, 0, 0, 0};
                mma_s8(crs, a0f[mf], b1f);
                mma_s8(crs, a1f[mf], b0f);
#pragma unroll
                for (int r = 0; r < 4; r++)
                    acc[mf][nf][r] += (crs[r] + 64) >> 7;
            }
        }
        __syncthreads();

        if (c + I8STAGES < nchunks) fill_stage(c + I8STAGES, s);
    }

    // Epilogue: dequantize with row/col scales
#pragma unroll
    for (int mf = 0; mf < 2; mf++) {
        const int r0 = brow + wm * 32 + mf * 16 + g;
        const float sa0 = sA[r0] * (1.f / 16129.f);
        const float sa1 = sA[r0 + 8] * (1.f / 16129.f);
#pragma unroll
        for (int nf = 0; nf < 8; nf++) {
            const int cc = bcol + wn * 64 + nf * 8 + 2 * t4;
            const float sb0 = sB[cc], sb1 = sB[cc + 1];
            *(float2*)&C[(size_t)r0 * N + cc] =
                make_float2((float)acc[mf][nf][0] * sa0 * sb0,
                            (float)acc[mf][nf][1] * sa0 * sb1);
            *(float2*)&C[(size_t)(r0 + 8) * N + cc] =
                make_float2((float)acc[mf][nf][2] * sa1 * sb0,
                            (float)acc[mf][nf][3] * sa1 * sb1);
        }
    }
}

// ===========================================================================
// bf16x3 GEMM (O-projection, proven mainloop). GSTAGES=2 -> 2 CTAs/SM.
// ===========================================================================
#define ROW_E   40
#define ROW_B   (ROW_E * 2)
#define ARR_B   (128 * ROW_B)
#define BSTAGE_B (4 * ARR_B)
#define GSTAGES 2
#define BGEMM_SMEM (GSTAGES * BSTAGE_B)

__global__ __launch_bounds__(256, 2) void bf16_gemm_kernel(
    const __nv_bfloat16* __restrict__ A0, const __nv_bfloat16* __restrict__ A1,
    const __nv_bfloat16* __restrict__ B0, const __nv_bfloat16* __restrict__ B1,
    float* __restrict__ C, int M, int N, int K)
{
    extern __shared__ char gsm[];
    const unsigned sbase = smem_u32(gsm);

    const int tid  = threadIdx.x;
    const int wid  = tid >> 5;
    const int lane = tid & 31;
    const int g    = lane >> 2;
    const int t4   = lane & 3;
    const int wm   = wid & 3;
    const int wn   = wid >> 2;

    const int brow = blockIdx.y * 128;
    const int bcol = blockIdx.x * 128;
    const int nchunks = K / 32;

    float acc[2][8][4];
#pragma unroll
    for (int mf = 0; mf < 2; mf++)
#pragma unroll
        for (int nf = 0; nf < 8; nf++)
#pragma unroll
            for (int r = 0; r < 4; r++) acc[mf][nf][r] = 0.f;

    const __nv_bfloat16* srcs[4] = {A0, A1, B0, B1};

    auto fill_stage = [&](int c, int s) {
        const int k0 = c * 32;
        const unsigned st = sbase + s * BSTAGE_B;
#pragma unroll
        for (int j = 0; j < 8; j++) {
            int idx = tid + j * 256;
            int arr = idx >> 9;
            int t   = idx & 511;
            int r   = t >> 2, u = t & 3;
            int grow = (arr < 2) ? (brow + r) : (bcol + r);
            const __nv_bfloat16* src = srcs[arr] + (size_t)grow * K + k0 + u * 8;
            CP_ASYNC16(st + (unsigned)(arr * ARR_B + r * ROW_B + u * 16), src);
        }
        CP_COMMIT();
    };

#pragma unroll
    for (int c = 0; c < GSTAGES; c++) fill_stage(c, c);

#pragma unroll 1
    for (int c = 0; c < nchunks; c++) {
        const int s = c & 1;
        const int rem = nchunks - 1 - c;
        if (rem >= 1) asm volatile("cp.async.wait_group 1;" ::: "memory");
        else          asm volatile("cp.async.wait_group 0;" ::: "memory");
        __syncthreads();

        const unsigned* sA0 = (const unsigned*)(gsm + s * BSTAGE_B);
        const unsigned* sA1 = (const unsigned*)(gsm + s * BSTAGE_B + ARR_B);
        const unsigned* sB0 = (const unsigned*)(gsm + s * BSTAGE_B + 2 * ARR_B);
        const unsigned* sB1 = (const unsigned*)(gsm + s * BSTAGE_B + 3 * ARR_B);
        const int ROW_W = ROW_B / 4;

#pragma unroll
        for (int ks = 0; ks < 2; ks++) {
            const int kw = ks * 8 + t4;
            unsigned a0f[2][4], a1f[2][4];
#pragma unroll
            for (int mf = 0; mf < 2; mf++) {
                const int r0 = wm * 32 + mf * 16 + g;
                a0f[mf][0] = sA0[r0 * ROW_W + kw];
                a0f[mf][1] = sA0[(r0 + 8) * ROW_W + kw];
                a0f[mf][2] = sA0[r0 * ROW_W + kw + 4];
                a0f[mf][3] = sA0[(r0 + 8) * ROW_W + kw + 4];
                a1f[mf][0] = sA1[r0 * ROW_W + kw];
                a1f[mf][1] = sA1[(r0 + 8) * ROW_W + kw];
                a1f[mf][2] = sA1[r0 * ROW_W + kw + 4];
                a1f[mf][3] = sA1[(r0 + 8) * ROW_W + kw + 4];
            }
#pragma unroll
            for (int nf = 0; nf < 8; nf++) {
                const int n = wn * 64 + nf * 8 + g;
                unsigned b0f[2], b1f[2];
                b0f[0] = sB0[n * ROW_W + kw];
                b0f[1] = sB0[n * ROW_W + kw + 4];
                b1f[0] = sB1[n * ROW_W + kw];
                b1f[1] = sB1[n * ROW_W + kw + 4];
#pragma unroll
                for (int mf = 0; mf < 2; mf++) {
                    mma_bf16(acc[mf][nf], a0f[mf], b0f);
                    mma_bf16(acc[mf][nf], a0f[mf], b1f);
                    mma_bf16(acc[mf][nf], a1f[mf], b0f);
                }
            }
        }
        __syncthreads();

        if (c + GSTAGES < nchunks) fill_stage(c + GSTAGES, s);
    }

#pragma unroll
    for (int mf = 0; mf < 2; mf++) {
        const int r0 = brow + wm * 32 + mf * 16 + g;
#pragma unroll
        for (int nf = 0; nf < 8; nf++) {
            const int cc = bcol + wn * 64 + nf * 8 + 2 * t4;
            *(float2*)&C[(size_t)r0 * N + cc] =
                make_float2(acc[mf][nf][0], acc[mf][nf][1]);
            *(float2*)&C[(size_t)(r0 + 8) * N + cc] =
                make_float2(acc[mf][nf][2], acc[mf][nf][3]);
        }
    }
}

// ===========================================================================
// Fused RMSNorm (+weight) + RoPE over merged [S][3072] QKV buffer.
// ===========================================================================
__global__ __launch_bounds__(256) void norm_rope_kernel(
    const float* __restrict__ qw, const float* __restrict__ kw,
    const float* __restrict__ cosb, const float* __restrict__ sinb,
    __nv_bfloat16* __restrict__ q0o, __nv_bfloat16* __restrict__ q1o,
    __nv_bfloat16* __restrict__ k0o, __nv_bfloat16* __restrict__ k1o)
{
    const int s    = blockIdx.x;
    const int slot = blockIdx.y;
    const int d    = threadIdx.x;

    const float* basep;
    const float* w = nullptr;
    bool do_rope = true;
    if (slot < 8)       { basep = g_qkv + (size_t)s * NQKV + slot * DH;                w = qw; }
    else if (slot < 10) { basep = g_qkv + (size_t)s * NQKV + 2048 + (slot - 8) * DH;   w = kw; }
    else                { basep = g_qkv + (size_t)s * NQKV + 2560 + (slot - 10) * DH;  do_rope = false; }

    float x  = basep[d];
    float v2 = x * x;
#pragma unroll
    for (int o = 16; o > 0; o >>= 1) v2 += __shfl_xor_sync(0xffffffffu, v2, o);

    __shared__ float wsum[8];
    __shared__ float ys[256];
    const int warp = d >> 5, lane = d & 31;
    if (lane == 0) wsum[warp] = v2;
    __syncthreads();
    float tot = 0.f;
#pragma unroll
    for (int i = 0; i < 8; i++) tot += wsum[i];

    float y = x * rsqrtf(tot * (1.0f / 256.0f) + 1e-6f);
    if (w) y *= w[d];

    if (do_rope) {
        ys[d] = y;
        __syncthreads();
        float rot = (d < 128) ? -ys[d + 128] : ys[d - 128];
        y = y * cosb[(size_t)s * DH + d] + rot * sinb[(size_t)s * DH + d];
    }

    if (slot < 8) {
        __nv_bfloat16 h, l;
        bf16_split(y, h, l);
        size_t off = (size_t)s * (NHQ * DH) + slot * DH + d;
        q0o[off] = h; q1o[off] = l;
    } else if (slot < 10) {
        __nv_bfloat16 h, l;
        bf16_split(y, h, l);
        size_t off = (size_t)s * (NKV * DH) + (slot - 8) * DH + d;
        k0o[off] = h; k1o[off] = l;
    } else {
        ((float*)basep)[d] = y;   // v: fp32 in place (read by vsplit_t)
    }
}

// ===========================================================================
// MMA flash attention: QK bf16x3, PV fp16x1 (R12 proven).
// ===========================================================================
#define QROWW 132
#define VROWW 36
#define QW0_OFF 0
#define QW1_OFF (64 * QROWW)
#define KW0_OFF (2 * 64 * QROWW)
#define KW1_OFF (3 * 64 * QROWW)
#define VW0_OFF (4 * 64 * QROWW)
#define ATTN_SMEM_BYTES ((4 * 64 * QROWW + 256 * VROWW) * 4)

__global__ __launch_bounds__(128, 1) void attn_mma_kernel(
    const __nv_bfloat16* __restrict__ q0, const __nv_bfloat16* __restrict__ q1,
    const __nv_bfloat16* __restrict__ k0, const __nv_bfloat16* __restrict__ k1,
    const __half* __restrict__ vt,
    __nv_bfloat16* __restrict__ out0, __nv_bfloat16* __restrict__ out1)
{
    extern __shared__ unsigned smw[];
    const unsigned sbase = smem_u32(smw);
    const int tid = threadIdx.x;
    const int w = tid >> 5, lane = tid & 31;
    const int g = lane >> 2, t4 = lane & 3;
    const int qt = blockIdx.x, h = blockIdx.y, kvh = h >> 2;
    const int q0r = qt * 64;

#pragma unroll 4
    for (int j = 0; j < 32; j++) {
        int idx = tid + j * 128;
        int arr = idx >> 11, t = idx & 2047;
        int r = t >> 5, u = t & 31;
        const __nv_bfloat16* src = (arr ? q1 : q0) + (size_t)(q0r + r) * 2048 + h * 256 + u * 8;
        unsigned dst = sbase + (unsigned)(((arr ? QW1_OFF : QW0_OFF) + r * QROWW + u * 4) * 4);
        CP_ASYNC16(dst, src);
    }
    CP_COMMIT();

    float o[32][4];
#pragma unroll
    for (int nf = 0; nf < 32; nf++)
#pragma unroll
        for (int r = 0; r < 4; r++) o[nf][r] = 0.f;
    float m_g = -1e30f, m_g8 = -1e30f, l_g = 0.f, l_g8 = 0.f;

    const unsigned* QW0 = smw + QW0_OFF;
    const unsigned* QW1 = smw + QW1_OFF;
    const unsigned* KW0 = smw + KW0_OFF;
    const unsigned* KW1 = smw + KW1_OFF;
    const unsigned* VW0 = smw + VW0_OFF;

    const int qg_g  = q0r + 16 * w + g;
    const int qg_g8 = qg_g + 8;

    const int t0 = max(0, qt - 8);
#pragma unroll 1
    for (int kt = t0; kt <= qt; kt++) {
        const int kbase = kt * 64;
        __syncthreads();

#pragma unroll 4
        for (int j = 0; j < 32; j++) {
            int idx = tid + j * 128;
            int arr = idx >> 11, t = idx & 2047;
            int r = t >> 5, u = t & 31;
            const __nv_bfloat16* src = (arr ? k1 : k0) + (size_t)(kbase + r) * 512 + kvh * 256 + u * 8;
            unsigned dst = sbase + (unsigned)(((arr ? KW1_OFF : KW0_OFF) + r * QROWW + u * 4) * 4);
            CP_ASYNC16(dst, src);
        }
        CP_COMMIT();
#pragma unroll 4
        for (int j = 0; j < 16; j++) {
            int idx = tid + j * 128;
            int r = idx >> 3, u = idx & 7;
            const __half* src = vt + (size_t)(kvh * 256 + r) * 4096 + kbase + u * 8;
            unsigned dst = sbase + (unsigned)((VW0_OFF + r * VROWW + u * 4) * 4);
            CP_ASYNC16(dst, src);
        }
        CP_COMMIT();

        asm volatile("cp.async.wait_group 1;" ::: "memory");
        __syncthreads();

        float sc[8][4];
#pragma unroll
        for (int nf = 0; nf < 8; nf++)
#pragma unroll
            for (int r = 0; r < 4; r++) sc[nf][r] = 0.f;

#pragma unroll
        for (int ks = 0; ks < 16; ks++) {
            const int ra = (16 * w + g) * QROWW + 8 * ks + t4;
            const int rb = ra + 8 * QROWW;
            unsigned aH[4], aL[4];
            aH[0] = QW0[ra]; aH[1] = QW0[rb]; aH[2] = QW0[ra + 4]; aH[3] = QW0[rb + 4];
            aL[0] = QW1[ra]; aL[1] = QW1[rb]; aL[2] = QW1[ra + 4]; aL[3] = QW1[rb + 4];
#pragma unroll
            for (int nf = 0; nf < 8; nf++) {
                const int kb = (nf * 8 + g) * QROWW + 8 * ks + t4;
                unsigned bH[2] = {KW0[kb], KW0[kb + 4]};
                unsigned bL[2] = {KW1[kb], KW1[kb + 4]};
                mma_bf16(sc[nf], aH, bH);
                mma_bf16(sc[nf], aH, bL);
                mma_bf16(sc[nf], aL, bH);
            }
        }

#pragma unroll
        for (int nf = 0; nf < 8; nf++) {
            const int c0 = kbase + nf * 8 + 2 * t4;
            const int c1 = c0 + 1;
            if (!(c0 <= qg_g  && qg_g  - c0 < WINDOW)) sc[nf][0] = -1e30f;
            if (!(c1 <= qg_g  && qg_g  - c1 < WINDOW)) sc[nf][1] = -1e30f;
            if (!(c0 <= qg_g8 && qg_g8 - c0 < WINDOW)) sc[nf][2] = -1e30f;
            if (!(c1 <= qg_g8 && qg_g8 - c1 < WINDOW)) sc[nf][3] = -1e30f;
        }

        float mx0 = -1e30f, mx1 = -1e30f;
#pragma unroll
        for (int nf = 0; nf < 8; nf++) {
            mx0 = fmaxf(mx0, fmaxf(sc[nf][0], sc[nf][1]));
            mx1 = fmaxf(mx1, fmaxf(sc[nf][2], sc[nf][3]));
        }
        mx0 = fmaxf(mx0, __shfl_xor_sync(0xffffffffu, mx0, 1));
        mx0 = fmaxf(mx0, __shfl_xor_sync(0xffffffffu, mx0, 2));
        mx1 = fmaxf(mx1, __shfl_xor_sync(0xffffffffu, mx1, 1));
        mx1 = fmaxf(mx1, __shfl_xor_sync(0xffffffffu, mx1, 2));

        const float mn0 = fmaxf(m_g, mx0), mn1 = fmaxf(m_g8, mx1);
        const float s0 = __expf(m_g - mn0), s1 = __expf(m_g8 - mn1);
        m_g = mn0; m_g8 = mn1;

        float ls0 = 0.f, ls1 = 0.f;
#pragma unroll
        for (int nf = 0; nf < 8; nf++) {
            sc[nf][0] = __expf(sc[nf][0] - mn0);
            sc[nf][1] = __expf(sc[nf][1] - mn0);
            sc[nf][2] = __expf(sc[nf][2] - mn1);
            sc[nf][3] = __expf(sc[nf][3] - mn1);
            ls0 += sc[nf][0] + sc[nf][1];
            ls1 += sc[nf][2] + sc[nf][3];
        }
        ls0 += __shfl_xor_sync(0xffffffffu, ls0, 1);
        ls0 += __shfl_xor_sync(0xffffffffu, ls0, 2);
        ls1 += __shfl_xor_sync(0xffffffffu, ls1, 1);
        ls1 += __shfl_xor_sync(0xffffffffu, ls1, 2);
        l_g  = l_g  * s0 + ls0;
        l_g8 = l_g8 * s1 + ls1;

#pragma unroll
        for (int nf = 0; nf < 32; nf++) {
            o[nf][0] *= s0; o[nf][1] *= s0;
            o[nf][2] *= s1; o[nf][3] *= s1;
        }

        asm volatile("cp.async.wait_group 0;" ::: "memory");
        __syncthreads();

#pragma unroll
        for (int s = 0; s < 4; s++) {
            unsigned aH[4];
#pragma unroll
            for (int half = 0; half < 2; half++) {
                const float* pv = sc[2 * s + half];
                aH[2 * half]     = hpack2(pv[0], pv[1]);
                aH[2 * half + 1] = hpack2(pv[2], pv[3]);
            }
#pragma unroll
            for (int nf = 0; nf < 32; nf++) {
                const int vb = (nf * 8 + g) * VROWW + 8 * s + t4;
                unsigned bH[2] = {VW0[vb], VW0[vb + 4]};
                mma_f16(o[nf], aH, bH);
            }
        }
    }

    const float i0 = 1.f / l_g, i1 = 1.f / l_g8;
    const int colb = h * 256 + 2 * t4;
#pragma unroll
    for (int nf = 0; nf < 32; nf++) {
        const int cc = colb + nf * 8;
        __nv_bfloat16 h0, l0, h1, l1;
        bf16_split(o[nf][0] * i0, h0, l0);
        bf16_split(o[nf][1] * i0, h1, l1);
        *(__nv_bfloat162*)&out0[(size_t)qg_g * 2048 + cc] = __nv_bfloat162(h0, h1);
        *(__nv_bfloat162*)&out1[(size_t)qg_g * 2048 + cc] = __nv_bfloat162(l0, l1);
        bf16_split(o[nf][2] * i1, h0, l0);
        bf16_split(o[nf][3] * i1, h1, l1);
        *(__nv_bfloat162*)&out0[(size_t)qg_g8 * 2048 + cc] = __nv_bfloat162(h0, h1);
        *(__nv_bfloat162*)&out1[(size_t)qg_g8 * 2048 + cc] = __nv_bfloat162(l0, l1);
    }
}

// ===========================================================================
extern "C" void kernel_launch(void* const* d_in, const int* in_sizes, int n_in,
                              void* d_out, int out_size)
{
    (void)in_sizes; (void)n_in; (void)out_size;
    const float* hs   = (const float*)d_in[0];
    const float* w_q  = (const float*)d_in[1];
    const float* w_k  = (const float*)d_in[2];
    const float* w_v  = (const float*)d_in[3];
    const float* w_o  = (const float*)d_in[4];
    const float* qw   = (const float*)d_in[5];
    const float* kw   = (const float*)d_in[6];
    const float* cosb = (const float*)d_in[7];
    const float* sinb = (const float*)d_in[8];
    float* out = (float*)d_out;

    float *gqkv, *sa, *sb;
    signed char *ha0, *ha1, *wq0, *wq1;
    __nv_bfloat16 *a0, *a1, *o0, *o1, *wo0, *wo1, *k0s, *k1s;
    __half* vt;
    cudaGetSymbolAddress((void**)&gqkv, g_qkv);
    cudaGetSymbolAddress((void**)&sa, g_sa);
    cudaGetSymbolAddress((void**)&sb, g_sb);
    cudaGetSymbolAddress((void**)&ha0, g_ha0);
    cudaGetSymbolAddress((void**)&ha1, g_ha1);
    cudaGetSymbolAddress((void**)&wq0, g_wq0);
    cudaGetSymbolAddress((void**)&wq1, g_wq1);
    cudaGetSymbolAddress((void**)&a0, g_a0);
    cudaGetSymbolAddress((void**)&a1, g_a1);
    cudaGetSymbolAddress((void**)&o0, g_o0);
    cudaGetSymbolAddress((void**)&o1, g_o1);
    cudaGetSymbolAddress((void**)&wo0, g_wo0);
    cudaGetSymbolAddress((void**)&wo1, g_wo1);
    cudaGetSymbolAddress((void**)&k0s, g_k0s);
    cudaGetSymbolAddress((void**)&k1s, g_k1s);
    cudaGetSymbolAddress((void**)&vt, g_vt);

    cudaFuncSetAttribute(i8_gemm_kernel, cudaFuncAttributeMaxDynamicSharedMemorySize, I8GEMM_SMEM);
    cudaFuncSetAttribute(bf16_gemm_kernel, cudaFuncAttributeMaxDynamicSharedMemorySize, BGEMM_SMEM);
    cudaFuncSetAttribute(attn_mma_kernel, cudaFuncAttributeMaxDynamicSharedMemorySize, ATTN_SMEM_BYTES);

    // --- quantize activations + weights for int8 QKV GEMM ---
    quant_rows_kernel<<<S_LEN, 256>>>(hs, ha0, ha1, sa, HDIM);
    colmax_kernel<<<(HDIM + 255) / 256, 256>>>(w_q, sb, HDIM, HDIM);
    colmax_kernel<<<((NKV * DH) + 255) / 256, 256>>>(w_k, sb + 2048, HDIM, NKV * DH);
    colmax_kernel<<<((NKV * DH) + 255) / 256, 256>>>(w_v, sb + 2560, HDIM, NKV * DH);
    tquant_kernel<<<dim3(HDIM / 32, HDIM / 32), dim3(32, 8)>>>(
        w_q, wq0, wq1, sb, HDIM, HDIM);
    tquant_kernel<<<dim3((NKV * DH) / 32, HDIM / 32), dim3(32, 8)>>>(
        w_k, wq0 + (size_t)2048 * HDIM, wq1 + (size_t)2048 * HDIM, sb + 2048, HDIM, NKV * DH);
    tquant_kernel<<<dim3((NKV * DH) / 32, HDIM / 32), dim3(32, 8)>>>(
        w_v, wq0 + (size_t)2560 * HDIM, wq1 + (size_t)2560 * HDIM, sb + 2560, HDIM, NKV * DH);
    tsplit_kernel<<<dim3(HDIM / 32, HDIM / 32), dim3(32, 8)>>>(w_o, wo0, wo1, HDIM, HDIM);

    // --- merged QKV projection (int8 Ozaki, k32 MMAs) ---
    i8_gemm_kernel<<<dim3(NQKV / 128, S_LEN / 128), 256, I8GEMM_SMEM>>>(
        ha0, ha1, wq0, wq1, sa, sb, gqkv, S_LEN, NQKV, HDIM);

    // --- RMSNorm + RoPE, q/k bf16 splits ---
    norm_rope_kernel<<<dim3(S_LEN, NHQ + 2 * NKV), 256>>>(
        qw, kw, cosb, sinb, a0, a1, k0s, k1s);

    // --- transpose v to fp16 ---
    vsplit_t_kernel<<<dim3(S_LEN / 32, DH / 32, NKV), dim3(32, 8)>>>(gqkv, vt);

    // --- MMA flash attention (QK bf16x3, PV fp16x1) ---
    attn_mma_kernel<<<dim3(S_LEN / 64, NHQ), 128, ATTN_SMEM_BYTES>>>(
        a0, a1, k0s, k1s, vt, o0, o1);

    // --- O-projection (bf16x3) ---
    bf16_gemm_kernel<<<dim3(HDIM / 128, S_LEN / 128), 256, BGEMM_SMEM>>>(
        o0, o1, wo0, wo1, out, S_LEN, HDIM, HDIM);
}

// round 15
// speedup vs baseline: 1.8429x; 1.8429x over previous
#include <cuda_runtime.h>
#include <cuda_bf16.h>
#include <cuda_fp16.h>
#include <math.h>

#define S_LEN  4096
#define HDIM   2048
#define NHQ    8
#define NKV    2
#define DH     256
#define WINDOW 512
#define NQKV   3072

// fp32 scratch: merged QKV projection output [S][3072]
__device__ float g_qkv[S_LEN * NQKV];

// fp16 scratch
__device__ __half g_a0[S_LEN * HDIM];        // hs fp16 hi -> q fp16 hi
__device__ __half g_a1[S_LEN * HDIM];        // hs fp16 lo -> q fp16 lo
__device__ __half g_o0[S_LEN * HDIM];        // attn out fp16 hi
__device__ __half g_o1[S_LEN * HDIM];        // attn out fp16 lo
__device__ __half g_wqkv0[NQKV * HDIM];      // merged weights fp16 hi [n][k]
__device__ __half g_wqkv1[NQKV * HDIM];      // merged weights fp16 lo [n][k]
__device__ __half g_wo0[HDIM * HDIM];
__device__ __half g_wo1[HDIM * HDIM];
__device__ __half g_k0s[S_LEN * NKV * DH];
__device__ __half g_k1s[S_LEN * NKV * DH];
__device__ __half g_vt[NKV * DH * S_LEN];    // v fp16 [h][d][s]

// ===========================================================================
// Helpers
// ===========================================================================
__device__ __forceinline__ unsigned smem_u32(const void* p) {
    unsigned a;
    asm("{ .reg .u64 t; cvta.to.shared.u64 t, %1; cvt.u32.u64 %0, t; }"
        : "=r"(a) : "l"(p));
    return a;
}

#define CP_ASYNC16(dst, src) \
    asm volatile("cp.async.cg.shared.global [%0], [%1], 16;" :: "r"(dst), "l"(src) : "memory")
#define CP_COMMIT() asm volatile("cp.async.commit_group;" ::: "memory")

__device__ __forceinline__ void fp16_split(float x, __half& h, __half& l) {
    h = __float2half_rn(x);
    l = __float2half_rn(x - __half2float(h));
}

__device__ __forceinline__ unsigned hpack2(float x, float y) {
    __half2 p = __floats2half2_rn(x, y);
    return *(unsigned*)&p;
}

// fp16 inputs, fp32 accumulators
__device__ __forceinline__ void mma_f16(float* d, const unsigned* a, const unsigned* b) {
    asm volatile(
        "mma.sync.aligned.m16n8k16.row.col.f32.f16.f16.f32 "
        "{%0,%1,%2,%3}, {%4,%5,%6,%7}, {%8,%9}, {%0,%1,%2,%3};"
        : "+f"(d[0]), "+f"(d[1]), "+f"(d[2]), "+f"(d[3])
        : "r"(a[0]), "r"(a[1]), "r"(a[2]), "r"(a[3]), "r"(b[0]), "r"(b[1]));
}

// fp16 inputs, fp16 accumulators (2 packed regs)
__device__ __forceinline__ void mma_f16h(unsigned* d, const unsigned* a, const unsigned* b) {
    asm volatile(
        "mma.sync.aligned.m16n8k16.row.col.f16.f16.f16.f16 "
        "{%0,%1}, {%2,%3,%4,%5}, {%6,%7}, {%0,%1};"
        : "+r"(d[0]), "+r"(d[1])
        : "r"(a[0]), "r"(a[1]), "r"(a[2]), "r"(a[3]), "r"(b[0]), "r"(b[1]));
}

// ===========================================================================
// Split: fp32 [n] -> fp16 hi/lo planar. 4 elems/thread.
// ===========================================================================
__global__ __launch_bounds__(256) void split_h_kernel(
    const float* __restrict__ in, __half* __restrict__ o0,
    __half* __restrict__ o1, int n)
{
    int i = (blockIdx.x * 256 + threadIdx.x) * 4;
    if (i >= n) return;
    float4 v = *(const float4*)(in + i);
    __half h0, l0, h1, l1, h2, l2, h3, l3;
    fp16_split(v.x, h0, l0); fp16_split(v.y, h1, l1);
    fp16_split(v.z, h2, l2); fp16_split(v.w, h3, l3);
    __half2* p0 = (__half2*)(o0 + i);
    __half2* p1 = (__half2*)(o1 + i);
    p0[0] = __half2(h0, h1); p0[1] = __half2(h2, h3);
    p1[0] = __half2(l0, l1); p1[1] = __half2(l2, l3);
}

// ===========================================================================
// Transpose-split: fp32 B [K][N] -> fp16 hi/lo [N][K] x2.
// ===========================================================================
__global__ __launch_bounds__(256) void tsplit_h2_kernel(
    const float* __restrict__ in, __half* __restrict__ o0,
    __half* __restrict__ o1, int K, int N)
{
    __shared__ float tile[32][33];
    const int n0 = blockIdx.x * 32;
    const int k0 = blockIdx.y * 32;
    const int tx = threadIdx.x, ty = threadIdx.y;
#pragma unroll
    for (int j = 0; j < 4; j++)
        tile[ty + 8 * j][tx] = in[(size_t)(k0 + ty + 8 * j) * N + n0 + tx];
    __syncthreads();
#pragma unroll
    for (int j = 0; j < 4; j++) {
        int ny = ty + 8 * j;
        __half h, l;
        fp16_split(tile[tx][ny], h, l);
        size_t off = (size_t)(n0 + ny) * K + k0 + tx;
        o0[off] = h;
        o1[off] = l;
    }
}

// ===========================================================================
// V transpose: g_qkv [S][3072] (v at col 2560+) -> fp16 vt [h][DH][S].
// ===========================================================================
__global__ __launch_bounds__(256) void vsplit_t_kernel(
    const float* __restrict__ in, __half* __restrict__ o0)
{
    __shared__ float tile[32][33];
    const int s0 = blockIdx.x * 32;
    const int d0 = blockIdx.y * 32;
    const int hh = blockIdx.z;
    const int tx = threadIdx.x, ty = threadIdx.y;
#pragma unroll
    for (int j = 0; j < 4; j++)
        tile[ty + 8 * j][tx] =
            in[(size_t)(s0 + ty + 8 * j) * NQKV + 2560 + hh * DH + d0 + tx];
    __syncthreads();
#pragma unroll
    for (int j = 0; j < 4; j++) {
        int dy = ty + 8 * j;
        o0[(size_t)(hh * DH + d0 + dy) * S_LEN + s0 + tx] =
            __float2half_rn(tile[tx][dy]);
    }
}

// ===========================================================================
// fp16x3 GEMM with f16-accum corrections:
// C = A0B0 (f32 acc) + [A0B1 + A1B0] (f16 acc, folded per (mf,nf,ks)).
// BM=128, BN=128, BK=32, 256 threads = 8 warps (4m x 2n), GSTAGES=2.
// ===========================================================================
#define ROW_E   40
#define ROW_B   (ROW_E * 2)                 // 80 bytes per smem row
#define ARR_B   (128 * ROW_B)               // 10240
#define STAGE_B (4 * ARR_B)                 // 40960 (A0, A1, B0, B1)
#define GSTAGES 2
#define GEMM_SMEM (GSTAGES * STAGE_B)       // 81920

__global__ __launch_bounds__(256, 2) void f16x3_gemm_kernel(
    const __half* __restrict__ A0, const __half* __restrict__ A1,
    const __half* __restrict__ B0, const __half* __restrict__ B1,
    float* __restrict__ C, int M, int N, int K)
{
    extern __shared__ char gsm[];
    const unsigned sbase = smem_u32(gsm);

    const int tid  = threadIdx.x;
    const int wid  = tid >> 5;
    const int lane = tid & 31;
    const int g    = lane >> 2;
    const int t4   = lane & 3;
    const int wm   = wid & 3;
    const int wn   = wid >> 2;

    const int brow = blockIdx.y * 128;
    const int bcol = blockIdx.x * 128;
    const int nchunks = K / 32;

    float acc[2][8][4];
#pragma unroll
    for (int mf = 0; mf < 2; mf++)
#pragma unroll
        for (int nf = 0; nf < 8; nf++)
#pragma unroll
            for (int r = 0; r < 4; r++) acc[mf][nf][r] = 0.f;

    const __half* srcs[4] = {A0, A1, B0, B1};

    auto fill_stage = [&](int c, int s) {
        const int k0 = c * 32;
        const unsigned st = sbase + s * STAGE_B;
#pragma unroll
        for (int j = 0; j < 8; j++) {
            int idx = tid + j * 256;
            int arr = idx >> 9;
            int t   = idx & 511;
            int r   = t >> 2, u = t & 3;
            int grow = (arr < 2) ? (brow + r) : (bcol + r);
            const __half* src = srcs[arr] + (size_t)grow * K + k0 + u * 8;
            CP_ASYNC16(st + (unsigned)(arr * ARR_B + r * ROW_B + u * 16), src);
        }
        CP_COMMIT();
    };

#pragma unroll
    for (int c = 0; c < GSTAGES; c++) fill_stage(c, c);

#pragma unroll 1
    for (int c = 0; c < nchunks; c++) {
        const int s = c & 1;
        const int rem = nchunks - 1 - c;
        if (rem >= 1) asm volatile("cp.async.wait_group 1;" ::: "memory");
        else          asm volatile("cp.async.wait_group 0;" ::: "memory");
        __syncthreads();

        const unsigned* sA0 = (const unsigned*)(gsm + s * STAGE_B);
        const unsigned* sA1 = (const unsigned*)(gsm + s * STAGE_B + ARR_B);
        const unsigned* sB0 = (const unsigned*)(gsm + s * STAGE_B + 2 * ARR_B);
        const unsigned* sB1 = (const unsigned*)(gsm + s * STAGE_B + 3 * ARR_B);
        const int ROW_W = ROW_B / 4;   // 20 words per row

#pragma unroll
        for (int ks = 0; ks < 2; ks++) {
            const int kw = ks * 8 + t4;
            unsigned a0f[2][4], a1f[2][4];
#pragma unroll
            for (int mf = 0; mf < 2; mf++) {
                const int r0 = wm * 32 + mf * 16 + g;
                a0f[mf][0] = sA0[r0 * ROW_W + kw];
                a0f[mf][1] = sA0[(r0 + 8) * ROW_W + kw];
                a0f[mf][2] = sA0[r0 * ROW_W + kw + 4];
                a0f[mf][3] = sA0[(r0 + 8) * ROW_W + kw + 4];
                a1f[mf][0] = sA1[r0 * ROW_W + kw];
                a1f[mf][1] = sA1[(r0 + 8) * ROW_W + kw];
                a1f[mf][2] = sA1[r0 * ROW_W + kw + 4];
                a1f[mf][3] = sA1[(r0 + 8) * ROW_W + kw + 4];
            }
#pragma unroll
            for (int nf = 0; nf < 8; nf++) {
                const int n = wn * 64 + nf * 8 + g;
                unsigned b0f[2], b1f[2];
                b0f[0] = sB0[n * ROW_W + kw];
                b0f[1] = sB0[n * ROW_W + kw + 4];
                b1f[0] = sB1[n * ROW_W + kw];
                b1f[1] = sB1[n * ROW_W + kw + 4];
#pragma unroll
                for (int mf = 0; mf < 2; mf++) {
                    // main term, f32 accumulation
                    mma_f16(acc[mf][nf], a0f[mf], b0f);
                    // correction terms, f16 accumulation (2^-11 scale)
                    unsigned cc[2] = {0u, 0u};
                    mma_f16h(cc, a0f[mf], b1f);
                    mma_f16h(cc, a1f[mf], b0f);
                    float2 f0 = __half22float2(*(__half2*)&cc[0]);
                    float2 f1 = __half22float2(*(__half2*)&cc[1]);
                    acc[mf][nf][0] += f0.x; acc[mf][nf][1] += f0.y;
                    acc[mf][nf][2] += f1.x; acc[mf][nf][3] += f1.y;
                }
            }
        }
        __syncthreads();

        if (c + GSTAGES < nchunks) fill_stage(c + GSTAGES, s);
    }

#pragma unroll
    for (int mf = 0; mf < 2; mf++) {
        const int r0 = brow + wm * 32 + mf * 16 + g;
#pragma unroll
        for (int nf = 0; nf < 8; nf++) {
            const int cc = bcol + wn * 64 + nf * 8 + 2 * t4;
            *(float2*)&C[(size_t)r0 * N + cc] =
                make_float2(acc[mf][nf][0], acc[mf][nf][1]);
            *(float2*)&C[(size_t)(r0 + 8) * N + cc] =
                make_float2(acc[mf][nf][2], acc[mf][nf][3]);
        }
    }
}

// ===========================================================================
// Fused RMSNorm (+weight) + RoPE over merged [S][3072] QKV buffer.
// q -> fp16 hi/lo (a0/a1), k -> fp16 hi/lo (k0s/k1s), v -> fp32 in place
// ===========================================================================
__global__ __launch_bounds__(256) void norm_rope_kernel(
    const float* __restrict__ qw, const float* __restrict__ kw,
    const float* __restrict__ cosb, const float* __restrict__ sinb,
    __half* __restrict__ q0o, __half* __restrict__ q1o,
    __half* __restrict__ k0o, __half* __restrict__ k1o)
{
    const int s    = blockIdx.x;
    const int slot = blockIdx.y;
    const int d    = threadIdx.x;

    const float* basep;
    const float* w = nullptr;
    bool do_rope = true;
    if (slot < 8)       { basep = g_qkv + (size_t)s * NQKV + slot * DH;                w = qw; }
    else if (slot < 10) { basep = g_qkv + (size_t)s * NQKV + 2048 + (slot - 8) * DH;   w = kw; }
    else                { basep = g_qkv + (size_t)s * NQKV + 2560 + (slot - 10) * DH;  do_rope = false; }

    float x  = basep[d];
    float v2 = x * x;
#pragma unroll
    for (int o = 16; o > 0; o >>= 1) v2 += __shfl_xor_sync(0xffffffffu, v2, o);

    __shared__ float wsum[8];
    __shared__ float ys[256];
    const int warp = d >> 5, lane = d & 31;
    if (lane == 0) wsum[warp] = v2;
    __syncthreads();
    float tot = 0.f;
#pragma unroll
    for (int i = 0; i < 8; i++) tot += wsum[i];

    float y = x * rsqrtf(tot * (1.0f / 256.0f) + 1e-6f);
    if (w) y *= w[d];

    if (do_rope) {
        ys[d] = y;
        __syncthreads();
        float rot = (d < 128) ? -ys[d + 128] : ys[d - 128];
        y = y * cosb[(size_t)s * DH + d] + rot * sinb[(size_t)s * DH + d];
    }

    if (slot < 8) {
        __half h, l;
        fp16_split(y, h, l);
        size_t off = (size_t)s * (NHQ * DH) + slot * DH + d;
        q0o[off] = h; q1o[off] = l;
    } else if (slot < 10) {
        __half h, l;
        fp16_split(y, h, l);
        size_t off = (size_t)s * (NKV * DH) + (slot - 8) * DH + d;
        k0o[off] = h; k1o[off] = l;
    } else {
        ((float*)basep)[d] = y;   // v: fp32 in place (read by vsplit_t)
    }
}

// ===========================================================================
// MMA flash attention: QK fp16x3, PV fp16x1. Output fp16 hi/lo splits.
// grid (S/64, NHQ), block 128.
// SMEM words: Q0/Q1 [64][132], K0/K1 [64][132], VT fp16 [256][36]
// ===========================================================================
#define QROWW 132
#define VROWW 36
#define QW0_OFF 0
#define QW1_OFF (64 * QROWW)
#define KW0_OFF (2 * 64 * QROWW)
#define KW1_OFF (3 * 64 * QROWW)
#define VW0_OFF (4 * 64 * QROWW)
#define ATTN_SMEM_BYTES ((4 * 64 * QROWW + 256 * VROWW) * 4)   // 172032

__global__ __launch_bounds__(128, 1) void attn_mma_kernel(
    const __half* __restrict__ q0, const __half* __restrict__ q1,
    const __half* __restrict__ k0, const __half* __restrict__ k1,
    const __half* __restrict__ vt,
    __half* __restrict__ out0, __half* __restrict__ out1)
{
    extern __shared__ unsigned smw[];
    const unsigned sbase = smem_u32(smw);
    const int tid = threadIdx.x;
    const int w = tid >> 5, lane = tid & 31;
    const int g = lane >> 2, t4 = lane & 3;
    const int qt = blockIdx.x, h = blockIdx.y, kvh = h >> 2;
    const int q0r = qt * 64;

#pragma unroll 4
    for (int j = 0; j < 32; j++) {
        int idx = tid + j * 128;
        int arr = idx >> 11, t = idx & 2047;
        int r = t >> 5, u = t & 31;
        const __half* src = (arr ? q1 : q0) + (size_t)(q0r + r) * 2048 + h * 256 + u * 8;
        unsigned dst = sbase + (unsigned)(((arr ? QW1_OFF : QW0_OFF) + r * QROWW + u * 4) * 4);
        CP_ASYNC16(dst, src);
    }
    CP_COMMIT();

    float o[32][4];
#pragma unroll
    for (int nf = 0; nf < 32; nf++)
#pragma unroll
        for (int r = 0; r < 4; r++) o[nf][r] = 0.f;
    float m_g = -1e30f, m_g8 = -1e30f, l_g = 0.f, l_g8 = 0.f;

    const unsigned* QW0 = smw + QW0_OFF;
    const unsigned* QW1 = smw + QW1_OFF;
    const unsigned* KW0 = smw + KW0_OFF;
    const unsigned* KW1 = smw + KW1_OFF;
    const unsigned* VW0 = smw + VW0_OFF;

    const int qg_g  = q0r + 16 * w + g;
    const int qg_g8 = qg_g + 8;

    const int t0 = max(0, qt - 8);
#pragma unroll 1
    for (int kt = t0; kt <= qt; kt++) {
        const int kbase = kt * 64;
        __syncthreads();

#pragma unroll 4
        for (int j = 0; j < 32; j++) {
            int idx = tid + j * 128;
            int arr = idx >> 11, t = idx & 2047;
            int r = t >> 5, u = t & 31;
            const __half* src = (arr ? k1 : k0) + (size_t)(kbase + r) * 512 + kvh * 256 + u * 8;
            unsigned dst = sbase + (unsigned)(((arr ? KW1_OFF : KW0_OFF) + r * QROWW + u * 4) * 4);
            CP_ASYNC16(dst, src);
        }
        CP_COMMIT();
#pragma unroll 4
        for (int j = 0; j < 16; j++) {
            int idx = tid + j * 128;
            int r = idx >> 3, u = idx & 7;
            const __half* src = vt + (size_t)(kvh * 256 + r) * 4096 + kbase + u * 8;
            unsigned dst = sbase + (unsigned)((VW0_OFF + r * VROWW + u * 4) * 4);
            CP_ASYNC16(dst, src);
        }
        CP_COMMIT();

        asm volatile("cp.async.wait_group 1;" ::: "memory");
        __syncthreads();

        float sc[8][4];
#pragma unroll
        for (int nf = 0; nf < 8; nf++)
#pragma unroll
            for (int r = 0; r < 4; r++) sc[nf][r] = 0.f;

#pragma unroll
        for (int ks = 0; ks < 16; ks++) {
            const int ra = (16 * w + g) * QROWW + 8 * ks + t4;
            const int rb = ra + 8 * QROWW;
            unsigned aH[4], aL[4];
            aH[0] = QW0[ra]; aH[1] = QW0[rb]; aH[2] = QW0[ra + 4]; aH[3] = QW0[rb + 4];
            aL[0] = QW1[ra]; aL[1] = QW1[rb]; aL[2] = QW1[ra + 4]; aL[3] = QW1[rb + 4];
#pragma unroll
            for (int nf = 0; nf < 8; nf++) {
                const int kb = (nf * 8 + g) * QROWW + 8 * ks + t4;
                unsigned bH[2] = {KW0[kb], KW0[kb + 4]};
                unsigned bL[2] = {KW1[kb], KW1[kb + 4]};
                mma_f16(sc[nf], aH, bH);
                mma_f16(sc[nf], aH, bL);
                mma_f16(sc[nf], aL, bH);
            }
        }

#pragma unroll
        for (int nf = 0; nf < 8; nf++) {
            const int c0 = kbase + nf * 8 + 2 * t4;
            const int c1 = c0 + 1;
            if (!(c0 <= qg_g  && qg_g  - c0 < WINDOW)) sc[nf][0] = -1e30f;
            if (!(c1 <= qg_g  && qg_g  - c1 < WINDOW)) sc[nf][1] = -1e30f;
            if (!(c0 <= qg_g8 && qg_g8 - c0 < WINDOW)) sc[nf][2] = -1e30f;
            if (!(c1 <= qg_g8 && qg_g8 - c1 < WINDOW)) sc[nf][3] = -1e30f;
        }

        float mx0 = -1e30f, mx1 = -1e30f;
#pragma unroll
        for (int nf = 0; nf < 8; nf++) {
            mx0 = fmaxf(mx0, fmaxf(sc[nf][0], sc[nf][1]));
            mx1 = fmaxf(mx1, fmaxf(sc[nf][2], sc[nf][3]));
        }
        mx0 = fmaxf(mx0, __shfl_xor_sync(0xffffffffu, mx0, 1));
        mx0 = fmaxf(mx0, __shfl_xor_sync(0xffffffffu, mx0, 2));
        mx1 = fmaxf(mx1, __shfl_xor_sync(0xffffffffu, mx1, 1));
        mx1 = fmaxf(mx1, __shfl_xor_sync(0xffffffffu, mx1, 2));

        const float mn0 = fmaxf(m_g, mx0), mn1 = fmaxf(m_g8, mx1);
        const float s0 = __expf(m_g - mn0), s1 = __expf(m_g8 - mn1);
        m_g = mn0; m_g8 = mn1;

        float ls0 = 0.f, ls1 = 0.f;
#pragma unroll
        for (int nf = 0; nf < 8; nf++) {
            sc[nf][0] = __expf(sc[nf][0] - mn0);
            sc[nf][1] = __expf(sc[nf][1] - mn0);
            sc[nf][2] = __expf(sc[nf][2] - mn1);
            sc[nf][3] = __expf(sc[nf][3] - mn1);
            ls0 += sc[nf][0] + sc[nf][1];
            ls1 += sc[nf][2] + sc[nf][3];
        }
        ls0 += __shfl_xor_sync(0xffffffffu, ls0, 1);
        ls0 += __shfl_xor_sync(0xffffffffu, ls0, 2);
        ls1 += __shfl_xor_sync(0xffffffffu, ls1, 1);
        ls1 += __shfl_xor_sync(0xffffffffu, ls1, 2);
        l_g  = l_g  * s0 + ls0;
        l_g8 = l_g8 * s1 + ls1;

#pragma unroll
        for (int nf = 0; nf < 32; nf++) {
            o[nf][0] *= s0; o[nf][1] *= s0;
            o[nf][2] *= s1; o[nf][3] *= s1;
        }

        asm volatile("cp.async.wait_group 0;" ::: "memory");
        __syncthreads();

#pragma unroll
        for (int s = 0; s < 4; s++) {
            unsigned aH[4];
#pragma unroll
            for (int half = 0; half < 2; half++) {
                const float* pv = sc[2 * s + half];
                aH[2 * half]     = hpack2(pv[0], pv[1]);
                aH[2 * half + 1] = hpack2(pv[2], pv[3]);
            }
#pragma unroll
            for (int nf = 0; nf < 32; nf++) {
                const int vb = (nf * 8 + g) * VROWW + 8 * s + t4;
                unsigned bH[2] = {VW0[vb], VW0[vb + 4]};
                mma_f16(o[nf], aH, bH);
            }
        }
    }

    const float i0 = 1.f / l_g, i1 = 1.f / l_g8;
    const int colb = h * 256 + 2 * t4;
#pragma unroll
    for (int nf = 0; nf < 32; nf++) {
        const int cc = colb + nf * 8;
        __half h0, l0, h1, l1;
        fp16_split(o[nf][0] * i0, h0, l0);
        fp16_split(o[nf][1] * i0, h1, l1);
        *(__half2*)&out0[(size_t)qg_g * 2048 + cc] = __half2(h0, h1);
        *(__half2*)&out1[(size_t)qg_g * 2048 + cc] = __half2(l0, l1);
        fp16_split(o[nf][2] * i1, h0, l0);
        fp16_split(o[nf][3] * i1, h1, l1);
        *(__half2*)&out0[(size_t)qg_g8 * 2048 + cc] = __half2(h0, h1);
        *(__half2*)&out1[(size_t)qg_g8 * 2048 + cc] = __half2(l0, l1);
    }
}

// ===========================================================================
extern "C" void kernel_launch(void* const* d_in, const int* in_sizes, int n_in,
                              void* d_out, int out_size)
{
    (void)in_sizes; (void)n_in; (void)out_size;
    const float* hs   = (const float*)d_in[0];
    const float* w_q  = (const float*)d_in[1];
    const float* w_k  = (const float*)d_in[2];
    const float* w_v  = (const float*)d_in[3];
    const float* w_o  = (const float*)d_in[4];
    const float* qw   = (const float*)d_in[5];
    const float* kw   = (const float*)d_in[6];
    const float* cosb = (const float*)d_in[7];
    const float* sinb = (const float*)d_in[8];
    float* out = (float*)d_out;

    float* gqkv;
    __half *a0, *a1, *o0, *o1, *wqkv0, *wqkv1, *wo0, *wo1, *k0s, *k1s, *vt;
    cudaGetSymbolAddress((void**)&gqkv, g_qkv);
    cudaGetSymbolAddress((void**)&a0, g_a0);
    cudaGetSymbolAddress((void**)&a1, g_a1);
    cudaGetSymbolAddress((void**)&o0, g_o0);
    cudaGetSymbolAddress((void**)&o1, g_o1);
    cudaGetSymbolAddress((void**)&wqkv0, g_wqkv0);
    cudaGetSymbolAddress((void**)&wqkv1, g_wqkv1);
    cudaGetSymbolAddress((void**)&wo0, g_wo0);
    cudaGetSymbolAddress((void**)&wo1, g_wo1);
    cudaGetSymbolAddress((void**)&k0s, g_k0s);
    cudaGetSymbolAddress((void**)&k1s, g_k1s);
    cudaGetSymbolAddress((void**)&vt, g_vt);

    cudaFuncSetAttribute(f16x3_gemm_kernel, cudaFuncAttributeMaxDynamicSharedMemorySize, GEMM_SMEM);
    cudaFuncSetAttribute(attn_mma_kernel, cudaFuncAttributeMaxDynamicSharedMemorySize, ATTN_SMEM_BYTES);

    // --- pre-pass: hs fp16 hi/lo; weights fp16 hi/lo (transposed, merged) ---
    split_h_kernel<<<(S_LEN * HDIM / 4 + 255) / 256, 256>>>(hs, a0, a1, S_LEN * HDIM);
    tsplit_h2_kernel<<<dim3(HDIM / 32, HDIM / 32), dim3(32, 8)>>>(
        w_q, wqkv0, wqkv1, HDIM, HDIM);
    tsplit_h2_kernel<<<dim3((NKV * DH) / 32, HDIM / 32), dim3(32, 8)>>>(
        w_k, wqkv0 + (size_t)2048 * HDIM, wqkv1 + (size_t)2048 * HDIM, HDIM, NKV * DH);
    tsplit_h2_kernel<<<dim3((NKV * DH) / 32, HDIM / 32), dim3(32, 8)>>>(
        w_v, wqkv0 + (size_t)2560 * HDIM, wqkv1 + (size_t)2560 * HDIM, HDIM, NKV * DH);
    tsplit_h2_kernel<<<dim3(HDIM / 32, HDIM / 32), dim3(32, 8)>>>(w_o, wo0, wo1, HDIM, HDIM);

    // --- merged QKV projection (fp16x3, f16-accum corrections) ---
    f16x3_gemm_kernel<<<dim3(NQKV / 128, S_LEN / 128), 256, GEMM_SMEM>>>(
        a0, a1, wqkv0, wqkv1, gqkv, S_LEN, NQKV, HDIM);

    // --- RMSNorm + RoPE, q/k fp16 splits ---
    norm_rope_kernel<<<dim3(S_LEN, NHQ + 2 * NKV), 256>>>(
        qw, kw, cosb, sinb, a0, a1, k0s, k1s);

    // --- transpose v to fp16 ---
    vsplit_t_kernel<<<dim3(S_LEN / 32, DH / 32, NKV), dim3(32, 8)>>>(gqkv, vt);

    // --- MMA flash attention (QK fp16x3, PV fp16x1) ---
    attn_mma_kernel<<<dim3(S_LEN / 64, NHQ), 128, ATTN_SMEM_BYTES>>>(
        a0, a1, k0s, k1s, vt, o0, o1);

    // --- O-projection (fp16x3, f16-accum corrections) ---
    f16x3_gemm_kernel<<<dim3(HDIM / 128, S_LEN / 128), 256, GEMM_SMEM>>>(
        o0, o1, wo0, wo1, out, S_LEN, HDIM, HDIM);
}

// round 16
// speedup vs baseline: 2.2275x; 1.2087x over previous
#include <cuda_runtime.h>
#include <cuda_bf16.h>
#include <cuda_fp16.h>
#include <math.h>

#define S_LEN  4096
#define HDIM   2048
#define NHQ    8
#define NKV    2
#define DH     256
#define WINDOW 512
#define NQKV   3072

// fp32 scratch: merged QKV projection output [S][3072]
__device__ float g_qkv[S_LEN * NQKV];

// scratch
__device__ __nv_bfloat16 g_a0[S_LEN * HDIM];          // hs splits -> q splits
__device__ __nv_bfloat16 g_a1[S_LEN * HDIM];
__device__ __nv_bfloat16 g_o0[S_LEN * HDIM];          // attention output splits
__device__ __nv_bfloat16 g_o1[S_LEN * HDIM];
__device__ __nv_bfloat16 g_wqkv0[NQKV * HDIM];        // merged [n][k] weight splits
__device__ __nv_bfloat16 g_wqkv1[NQKV * HDIM];
__device__ __nv_bfloat16 g_wo0[HDIM * HDIM];
__device__ __nv_bfloat16 g_wo1[HDIM * HDIM];
__device__ __nv_bfloat16 g_k0s[S_LEN * NKV * DH];
__device__ __nv_bfloat16 g_k1s[S_LEN * NKV * DH];
__device__ __half        g_vt[NKV * DH * S_LEN];      // v fp16 [h][d][s]

// ===========================================================================
// Helpers
// ===========================================================================
__device__ __forceinline__ unsigned smem_u32(const void* p) {
    unsigned a;
    asm("{ .reg .u64 t; cvta.to.shared.u64 t, %1; cvt.u32.u64 %0, t; }"
        : "=r"(a) : "l"(p));
    return a;
}

#define CP_ASYNC16(dst, src) \
    asm volatile("cp.async.cg.shared.global [%0], [%1], 16;" :: "r"(dst), "l"(src) : "memory")
#define CP_COMMIT() asm volatile("cp.async.commit_group;" ::: "memory")

__device__ __forceinline__ void bf16_split(float x, __nv_bfloat16& h, __nv_bfloat16& l) {
    h = __float2bfloat16_rn(x);
    l = __float2bfloat16_rn(x - __bfloat162float(h));
}

__device__ __forceinline__ unsigned hpack2(float x, float y) {
    __half2 p = __floats2half2_rn(x, y);
    return *(unsigned*)&p;
}

__device__ __forceinline__ void mma_bf16(float* d, const unsigned* a, const unsigned* b) {
    asm volatile(
        "mma.sync.aligned.m16n8k16.row.col.f32.bf16.bf16.f32 "
        "{%0,%1,%2,%3}, {%4,%5,%6,%7}, {%8,%9}, {%0,%1,%2,%3};"
        : "+f"(d[0]), "+f"(d[1]), "+f"(d[2]), "+f"(d[3])
        : "r"(a[0]), "r"(a[1]), "r"(a[2]), "r"(a[3]), "r"(b[0]), "r"(b[1]));
}

__device__ __forceinline__ void mma_f16(float* d, const unsigned* a, const unsigned* b) {
    asm volatile(
        "mma.sync.aligned.m16n8k16.row.col.f32.f16.f16.f32 "
        "{%0,%1,%2,%3}, {%4,%5,%6,%7}, {%8,%9}, {%0,%1,%2,%3};"
        : "+f"(d[0]), "+f"(d[1]), "+f"(d[2]), "+f"(d[3])
        : "r"(a[0]), "r"(a[1]), "r"(a[2]), "r"(a[3]), "r"(b[0]), "r"(b[1]));
}

// ===========================================================================
// Split kernel: fp32 [n] -> hi/lo bf16 planar. 4 elems/thread.
// ===========================================================================
__global__ __launch_bounds__(256) void split_kernel(
    const float* __restrict__ in, __nv_bfloat16* __restrict__ o0,
    __nv_bfloat16* __restrict__ o1, int n)
{
    int i = (blockIdx.x * 256 + threadIdx.x) * 4;
    if (i >= n) return;
    float4 v = *(const float4*)(in + i);
    __nv_bfloat16 h0, l0, h1, l1, h2, l2, h3, l3;
    bf16_split(v.x, h0, l0); bf16_split(v.y, h1, l1);
    bf16_split(v.z, h2, l2); bf16_split(v.w, h3, l3);
    __nv_bfloat162* p0 = (__nv_bfloat162*)(o0 + i);
    __nv_bfloat162* p1 = (__nv_bfloat162*)(o1 + i);
    p0[0] = __nv_bfloat162(h0, h1); p0[1] = __nv_bfloat162(h2, h3);
    p1[0] = __nv_bfloat162(l0, l1); p1[1] = __nv_bfloat162(l2, l3);
}

// ===========================================================================
// Transpose-split (weights): fp32 B [K][N] -> hi/lo bf16 [N][K].
// ===========================================================================
__global__ __launch_bounds__(256) void tsplit_kernel(
    const float* __restrict__ in, __nv_bfloat16* __restrict__ o0,
    __nv_bfloat16* __restrict__ o1, int K, int N)
{
    __shared__ float tile[32][33];
    const int n0 = blockIdx.x * 32;
    const int k0 = blockIdx.y * 32;
    const int tx = threadIdx.x, ty = threadIdx.y;
#pragma unroll
    for (int j = 0; j < 4; j++)
        tile[ty + 8 * j][tx] = in[(size_t)(k0 + ty + 8 * j) * N + n0 + tx];
    __syncthreads();
#pragma unroll
    for (int j = 0; j < 4; j++) {
        int ny = ty + 8 * j;
        float x = tile[tx][ny];
        __nv_bfloat16 h, l;
        bf16_split(x, h, l);
        size_t off = (size_t)(n0 + ny) * K + k0 + tx;
        o0[off] = h;
        o1[off] = l;
    }
}

// ===========================================================================
// V transpose: g_qkv [S][3072] (v at col 2560+) -> fp16 vt [h][DH][S].
// ===========================================================================
__global__ __launch_bounds__(256) void vsplit_t_kernel(
    const float* __restrict__ in, __half* __restrict__ o0)
{
    __shared__ float tile[32][33];
    const int s0 = blockIdx.x * 32;
    const int d0 = blockIdx.y * 32;
    const int hh = blockIdx.z;
    const int tx = threadIdx.x, ty = threadIdx.y;
#pragma unroll
    for (int j = 0; j < 4; j++)
        tile[ty + 8 * j][tx] =
            in[(size_t)(s0 + ty + 8 * j) * NQKV + 2560 + hh * DH + d0 + tx];
    __syncthreads();
#pragma unroll
    for (int j = 0; j < 4; j++) {
        int dy = ty + 8 * j;
        o0[(size_t)(hh * DH + d0 + dy) * S_LEN + s0 + tx] =
            __float2half_rn(tile[tx][dy]);
    }
}

// ===========================================================================
// bf16x3 GEMM (proven mainloop). BM=128, BN=128, BK=32.
// 256 threads = 8 warps (4m x 2n), warp tile 32x64. GSTAGES=2 -> 2 CTAs/SM.
// ===========================================================================
#define ROW_E   40
#define ROW_B   (ROW_E * 2)                 // 80 bytes per smem row
#define ARR_B   (128 * ROW_B)
#define STAGE_B (4 * ARR_B)                 // 40960
#define GSTAGES 2
#define GEMM_SMEM (GSTAGES * STAGE_B)       // 81920

__global__ __launch_bounds__(256, 2) void bf16_gemm_kernel(
    const __nv_bfloat16* __restrict__ A0, const __nv_bfloat16* __restrict__ A1,
    const __nv_bfloat16* __restrict__ B0, const __nv_bfloat16* __restrict__ B1,
    float* __restrict__ C, int M, int N, int K)
{
    extern __shared__ char gsm[];
    const unsigned sbase = smem_u32(gsm);

    const int tid  = threadIdx.x;
    const int wid  = tid >> 5;
    const int lane = tid & 31;
    const int g    = lane >> 2;
    const int t4   = lane & 3;
    const int wm   = wid & 3;
    const int wn   = wid >> 2;

    const int brow = blockIdx.y * 128;
    const int bcol = blockIdx.x * 128;
    const int nchunks = K / 32;

    float acc[2][8][4];
#pragma unroll
    for (int mf = 0; mf < 2; mf++)
#pragma unroll
        for (int nf = 0; nf < 8; nf++)
#pragma unroll
            for (int r = 0; r < 4; r++) acc[mf][nf][r] = 0.f;

    const __nv_bfloat16* srcs[4] = {A0, A1, B0, B1};

    auto fill_stage = [&](int c, int s) {
        const int k0 = c * 32;
        const unsigned st = sbase + s * STAGE_B;
#pragma unroll
        for (int j = 0; j < 8; j++) {
            int idx = tid + j * 256;
            int arr = idx >> 9;
            int t   = idx & 511;
            int r   = t >> 2, u = t & 3;
            int grow = (arr < 2) ? (brow + r) : (bcol + r);
            const __nv_bfloat16* src = srcs[arr] + (size_t)grow * K + k0 + u * 8;
            CP_ASYNC16(st + (unsigned)(arr * ARR_B + r * ROW_B + u * 16), src);
        }
        CP_COMMIT();
    };

#pragma unroll
    for (int c = 0; c < GSTAGES; c++) fill_stage(c, c);

#pragma unroll 1
    for (int c = 0; c < nchunks; c++) {
        const int s = c & 1;
        const int rem = nchunks - 1 - c;
        if (rem >= 1) asm volatile("cp.async.wait_group 1;" ::: "memory");
        else          asm volatile("cp.async.wait_group 0;" ::: "memory");
        __syncthreads();

        const unsigned* sA0 = (const unsigned*)(gsm + s * STAGE_B);
        const unsigned* sA1 = (const unsigned*)(gsm + s * STAGE_B + ARR_B);
        const unsigned* sB0 = (const unsigned*)(gsm + s * STAGE_B + 2 * ARR_B);
        const unsigned* sB1 = (const unsigned*)(gsm + s * STAGE_B + 3 * ARR_B);
        const int ROW_W = ROW_B / 4;   // 20 words per row

#pragma unroll
        for (int ks = 0; ks < 2; ks++) {
            const int kw = ks * 8 + t4;
            unsigned a0f[2][4], a1f[2][4];
#pragma unroll
            for (int mf = 0; mf < 2; mf++) {
                const int r0 = wm * 32 + mf * 16 + g;
                a0f[mf][0] = sA0[r0 * ROW_W + kw];
                a0f[mf][1] = sA0[(r0 + 8) * ROW_W + kw];
                a0f[mf][2] = sA0[r0 * ROW_W + kw + 4];
                a0f[mf][3] = sA0[(r0 + 8) * ROW_W + kw + 4];
                a1f[mf][0] = sA1[r0 * ROW_W + kw];
                a1f[mf][1] = sA1[(r0 + 8) * ROW_W + kw];
                a1f[mf][2] = sA1[r0 * ROW_W + kw + 4];
                a1f[mf][3] = sA1[(r0 + 8) * ROW_W + kw + 4];
            }
#pragma unroll
            for (int nf = 0; nf < 8; nf++) {
                const int n = wn * 64 + nf * 8 + g;
                unsigned b0f[2], b1f[2];
                b0f[0] = sB0[n * ROW_W + kw];
                b0f[1] = sB0[n * ROW_W + kw + 4];
                b1f[0] = sB1[n * ROW_W + kw];
                b1f[1] = sB1[n * ROW_W + kw + 4];
#pragma unroll
                for (int mf = 0; mf < 2; mf++) {
                    mma_bf16(acc[mf][nf], a0f[mf], b0f);
                    mma_bf16(acc[mf][nf], a0f[mf], b1f);
                    mma_bf16(acc[mf][nf], a1f[mf], b0f);
                }
            }
        }
        __syncthreads();

        if (c + GSTAGES < nchunks) fill_stage(c + GSTAGES, s);
    }

#pragma unroll
    for (int mf = 0; mf < 2; mf++) {
        const int r0 = brow + wm * 32 + mf * 16 + g;
#pragma unroll
        for (int nf = 0; nf < 8; nf++) {
            const int cc = bcol + wn * 64 + nf * 8 + 2 * t4;
            *(float2*)&C[(size_t)r0 * N + cc] =
                make_float2(acc[mf][nf][0], acc[mf][nf][1]);
            *(float2*)&C[(size_t)(r0 + 8) * N + cc] =
                make_float2(acc[mf][nf][2], acc[mf][nf][3]);
        }
    }
}

// ===========================================================================
// Warp-per-vector fused RMSNorm (+weight) + RoPE over merged QKV buffer.
// Each warp owns one (s, slot) 256-dim vector; 8 floats/lane.
// No smem, no block syncs; rotate-half partner via shfl_xor(16).
// grid = S*12/8 blocks of 256 threads (8 warps).
// ===========================================================================
__global__ __launch_bounds__(256) void norm_rope_kernel(
    const float* __restrict__ qw, const float* __restrict__ kw,
    const float* __restrict__ cosb, const float* __restrict__ sinb,
    __nv_bfloat16* __restrict__ q0o, __nv_bfloat16* __restrict__ q1o,
    __nv_bfloat16* __restrict__ k0o, __nv_bfloat16* __restrict__ k1o)
{
    const int vid  = blockIdx.x * 8 + (threadIdx.x >> 5);
    const int lane = threadIdx.x & 31;
    const int s    = vid / 12;
    const int slot = vid % 12;
    const int d0   = lane * 8;

    const float* basep;
    const float* w = nullptr;
    bool do_rope = true;
    if (slot < 8)       { basep = g_qkv + (size_t)s * NQKV + slot * DH;                w = qw; }
    else if (slot < 10) { basep = g_qkv + (size_t)s * NQKV + 2048 + (slot - 8) * DH;   w = kw; }
    else                { basep = g_qkv + (size_t)s * NQKV + 2560 + (slot - 10) * DH;  do_rope = false; }

    float x[8];
    *(float4*)&x[0] = *(const float4*)(basep + d0);
    *(float4*)&x[4] = *(const float4*)(basep + d0 + 4);

    float ss = 0.f;
#pragma unroll
    for (int j = 0; j < 8; j++) ss += x[j] * x[j];
#pragma unroll
    for (int o = 16; o > 0; o >>= 1) ss += __shfl_xor_sync(0xffffffffu, ss, o);

    const float inv = rsqrtf(ss * (1.0f / 256.0f) + 1e-6f);

    float y[8];
    if (w) {
        float wv[8];
        *(float4*)&wv[0] = *(const float4*)(w + d0);
        *(float4*)&wv[4] = *(const float4*)(w + d0 + 4);
#pragma unroll
        for (int j = 0; j < 8; j++) y[j] = x[j] * inv * wv[j];
    } else {
#pragma unroll
        for (int j = 0; j < 8; j++) y[j] = x[j] * inv;
    }

    if (do_rope) {
        float cs[8], sn[8];
        *(float4*)&cs[0] = *(const float4*)(cosb + (size_t)s * DH + d0);
        *(float4*)&cs[4] = *(const float4*)(cosb + (size_t)s * DH + d0 + 4);
        *(float4*)&sn[0] = *(const float4*)(sinb + (size_t)s * DH + d0);
        *(float4*)&sn[4] = *(const float4*)(sinb + (size_t)s * DH + d0 + 4);
#pragma unroll
        for (int j = 0; j < 8; j++) {
            float part = __shfl_xor_sync(0xffffffffu, y[j], 16);
            float rot  = (lane < 16) ? -part : part;
            y[j] = y[j] * cs[j] + rot * sn[j];
        }
    }

    __nv_bfloat16 h[8], l[8];
#pragma unroll
    for (int j = 0; j < 8; j++) bf16_split(y[j], h[j], l[j]);

    if (slot < 8) {
        size_t off = (size_t)s * (NHQ * DH) + slot * DH + d0;
#pragma unroll
        for (int j = 0; j < 8; j += 2) {
            *(__nv_bfloat162*)(q0o + off + j) = __nv_bfloat162(h[j], h[j + 1]);
            *(__nv_bfloat162*)(q1o + off + j) = __nv_bfloat162(l[j], l[j + 1]);
        }
    } else if (slot < 10) {
        size_t off = (size_t)s * (NKV * DH) + (slot - 8) * DH + d0;
#pragma unroll
        for (int j = 0; j < 8; j += 2) {
            *(__nv_bfloat162*)(k0o + off + j) = __nv_bfloat162(h[j], h[j + 1]);
            *(__nv_bfloat162*)(k1o + off + j) = __nv_bfloat162(l[j], l[j + 1]);
        }
    } else {
        float* wb = (float*)basep + d0;
        *(float4*)&wb[0] = make_float4(y[0], y[1], y[2], y[3]);
        *(float4*)&wb[4] = make_float4(y[4], y[5], y[6], y[7]);
    }
}

// ===========================================================================
// MMA flash attention: QK bf16x3, PV fp16x1 (R12 proven).
// grid (S/64, NHQ), block 128. Epilogue writes bf16 hi/lo splits.
// SMEM words: Q0/Q1 [64][132], K0/K1 [64][132], VT fp16 [256][36]
// ===========================================================================
#define QROWW 132
#define VROWW 36
#define QW0_OFF 0
#define QW1_OFF (64 * QROWW)
#define KW0_OFF (2 * 64 * QROWW)
#define KW1_OFF (3 * 64 * QROWW)
#define VW0_OFF (4 * 64 * QROWW)
#define ATTN_SMEM_BYTES ((4 * 64 * QROWW + 256 * VROWW) * 4)   // 172032

__global__ __launch_bounds__(128, 1) void attn_mma_kernel(
    const __nv_bfloat16* __restrict__ q0, const __nv_bfloat16* __restrict__ q1,
    const __nv_bfloat16* __restrict__ k0, const __nv_bfloat16* __restrict__ k1,
    const __half* __restrict__ vt,
    __nv_bfloat16* __restrict__ out0, __nv_bfloat16* __restrict__ out1)
{
    extern __shared__ unsigned smw[];
    const unsigned sbase = smem_u32(smw);
    const int tid = threadIdx.x;
    const int w = tid >> 5, lane = tid & 31;
    const int g = lane >> 2, t4 = lane & 3;
    const int qt = blockIdx.x, h = blockIdx.y, kvh = h >> 2;
    const int q0r = qt * 64;

    // Q load (once)
#pragma unroll 4
    for (int j = 0; j < 32; j++) {
        int idx = tid + j * 128;
        int arr = idx >> 11, t = idx & 2047;
        int r = t >> 5, u = t & 31;
        const __nv_bfloat16* src = (arr ? q1 : q0) + (size_t)(q0r + r) * 2048 + h * 256 + u * 8;
        unsigned dst = sbase + (unsigned)(((arr ? QW1_OFF : QW0_OFF) + r * QROWW + u * 4) * 4);
        CP_ASYNC16(dst, src);
    }
    CP_COMMIT();

    float o[32][4];
#pragma unroll
    for (int nf = 0; nf < 32; nf++)
#pragma unroll
        for (int r = 0; r < 4; r++) o[nf][r] = 0.f;
    float m_g = -1e30f, m_g8 = -1e30f, l_g = 0.f, l_g8 = 0.f;

    const unsigned* QW0 = smw + QW0_OFF;
    const unsigned* QW1 = smw + QW1_OFF;
    const unsigned* KW0 = smw + KW0_OFF;
    const unsigned* KW1 = smw + KW1_OFF;
    const unsigned* VW0 = smw + VW0_OFF;

    const int qg_g  = q0r + 16 * w + g;
    const int qg_g8 = qg_g + 8;

    const int t0 = max(0, qt - 8);
#pragma unroll 1
    for (int kt = t0; kt <= qt; kt++) {
        const int kbase = kt * 64;
        __syncthreads();

        // K tiles (group A)
#pragma unroll 4
        for (int j = 0; j < 32; j++) {
            int idx = tid + j * 128;
            int arr = idx >> 11, t = idx & 2047;
            int r = t >> 5, u = t & 31;
            const __nv_bfloat16* src = (arr ? k1 : k0) + (size_t)(kbase + r) * 512 + kvh * 256 + u * 8;
            unsigned dst = sbase + (unsigned)(((arr ? KW1_OFF : KW0_OFF) + r * QROWW + u * 4) * 4);
            CP_ASYNC16(dst, src);
        }
        CP_COMMIT();
        // V tile (group B): fp16, 256 rows x 8 units
#pragma unroll 4
        for (int j = 0; j < 16; j++) {
            int idx = tid + j * 128;
            int r = idx >> 3, u = idx & 7;
            const __half* src = vt + (size_t)(kvh * 256 + r) * 4096 + kbase + u * 8;
            unsigned dst = sbase + (unsigned)((VW0_OFF + r * VROWW + u * 4) * 4);
            CP_ASYNC16(dst, src);
        }
        CP_COMMIT();

        asm volatile("cp.async.wait_group 1;" ::: "memory");
        __syncthreads();

        // ---- scores S[16][64] (bf16x3) ----
        float sc[8][4];
#pragma unroll
        for (int nf = 0; nf < 8; nf++)
#pragma unroll
            for (int r = 0; r < 4; r++) sc[nf][r] = 0.f;

#pragma unroll
        for (int ks = 0; ks < 16; ks++) {
            const int ra = (16 * w + g) * QROWW + 8 * ks + t4;
            const int rb = ra + 8 * QROWW;
            unsigned aH[4], aL[4];
            aH[0] = QW0[ra]; aH[1] = QW0[rb]; aH[2] = QW0[ra + 4]; aH[3] = QW0[rb + 4];
            aL[0] = QW1[ra]; aL[1] = QW1[rb]; aL[2] = QW1[ra + 4]; aL[3] = QW1[rb + 4];
#pragma unroll
            for (int nf = 0; nf < 8; nf++) {
                const int kb = (nf * 8 + g) * QROWW + 8 * ks + t4;
                unsigned bH[2] = {KW0[kb], KW0[kb + 4]};
                unsigned bL[2] = {KW1[kb], KW1[kb + 4]};
                mma_bf16(sc[nf], aH, bH);
                mma_bf16(sc[nf], aH, bL);
                mma_bf16(sc[nf], aL, bH);
            }
        }

        // ---- mask ----
#pragma unroll
        for (int nf = 0; nf < 8; nf++) {
            const int c0 = kbase + nf * 8 + 2 * t4;
            const int c1 = c0 + 1;
            if (!(c0 <= qg_g  && qg_g  - c0 < WINDOW)) sc[nf][0] = -1e30f;
            if (!(c1 <= qg_g  && qg_g  - c1 < WINDOW)) sc[nf][1] = -1e30f;
            if (!(c0 <= qg_g8 && qg_g8 - c0 < WINDOW)) sc[nf][2] = -1e30f;
            if (!(c1 <= qg_g8 && qg_g8 - c1 < WINDOW)) sc[nf][3] = -1e30f;
        }

        // ---- online softmax ----
        float mx0 = -1e30f, mx1 = -1e30f;
#pragma unroll
        for (int nf = 0; nf < 8; nf++) {
            mx0 = fmaxf(mx0, fmaxf(sc[nf][0], sc[nf][1]));
            mx1 = fmaxf(mx1, fmaxf(sc[nf][2], sc[nf][3]));
        }
        mx0 = fmaxf(mx0, __shfl_xor_sync(0xffffffffu, mx0, 1));
        mx0 = fmaxf(mx0, __shfl_xor_sync(0xffffffffu, mx0, 2));
        mx1 = fmaxf(mx1, __shfl_xor_sync(0xffffffffu, mx1, 1));
        mx1 = fmaxf(mx1, __shfl_xor_sync(0xffffffffu, mx1, 2));

        const float mn0 = fmaxf(m_g, mx0), mn1 = fmaxf(m_g8, mx1);
        const float s0 = __expf(m_g - mn0), s1 = __expf(m_g8 - mn1);
        m_g = mn0; m_g8 = mn1;

        float ls0 = 0.f, ls1 = 0.f;
#pragma unroll
        for (int nf = 0; nf < 8; nf++) {
            sc[nf][0] = __expf(sc[nf][0] - mn0);
            sc[nf][1] = __expf(sc[nf][1] - mn0);
            sc[nf][2] = __expf(sc[nf][2] - mn1);
            sc[nf][3] = __expf(sc[nf][3] - mn1);
            ls0 += sc[nf][0] + sc[nf][1];
            ls1 += sc[nf][2] + sc[nf][3];
        }
        ls0 += __shfl_xor_sync(0xffffffffu, ls0, 1);
        ls0 += __shfl_xor_sync(0xffffffffu, ls0, 2);
        ls1 += __shfl_xor_sync(0xffffffffu, ls1, 1);
        ls1 += __shfl_xor_sync(0xffffffffu, ls1, 2);
        l_g  = l_g  * s0 + ls0;
        l_g8 = l_g8 * s1 + ls1;

#pragma unroll
        for (int nf = 0; nf < 32; nf++) {
            o[nf][0] *= s0; o[nf][1] *= s0;
            o[nf][2] *= s1; o[nf][3] *= s1;
        }

        asm volatile("cp.async.wait_group 0;" ::: "memory");
        __syncthreads();

        // ---- PV: O += P @ V (fp16 P, fp16 V, 1 MMA) ----
#pragma unroll
        for (int s = 0; s < 4; s++) {
            unsigned aH[4];
#pragma unroll
            for (int half = 0; half < 2; half++) {
                const float* pv = sc[2 * s + half];
                aH[2 * half]     = hpack2(pv[0], pv[1]);
                aH[2 * half + 1] = hpack2(pv[2], pv[3]);
            }
#pragma unroll
            for (int nf = 0; nf < 32; nf++) {
                const int vb = (nf * 8 + g) * VROWW + 8 * s + t4;
                unsigned bH[2] = {VW0[vb], VW0[vb + 4]};
                mma_f16(o[nf], aH, bH);
            }
        }
    }

    // ---- epilogue: normalized output as bf16 hi/lo splits ----
    const float i0 = 1.f / l_g, i1 = 1.f / l_g8;
    const int colb = h * 256 + 2 * t4;
#pragma unroll
    for (int nf = 0; nf < 32; nf++) {
        const int cc = colb + nf * 8;
        __nv_bfloat16 h0, l0, h1, l1;
        bf16_split(o[nf][0] * i0, h0, l0);
        bf16_split(o[nf][1] * i0, h1, l1);
        *(__nv_bfloat162*)&out0[(size_t)qg_g * 2048 + cc] = __nv_bfloat162(h0, h1);
        *(__nv_bfloat162*)&out1[(size_t)qg_g * 2048 + cc] = __nv_bfloat162(l0, l1);
        bf16_split(o[nf][2] * i1, h0, l0);
        bf16_split(o[nf][3] * i1, h1, l1);
        *(__nv_bfloat162*)&out0[(size_t)qg_g8 * 2048 + cc] = __nv_bfloat162(h0, h1);
        *(__nv_bfloat162*)&out1[(size_t)qg_g8 * 2048 + cc] = __nv_bfloat162(l0, l1);
    }
}

// ===========================================================================
extern "C" void kernel_launch(void* const* d_in, const int* in_sizes, int n_in,
                              void* d_out, int out_size)
{
    (void)in_sizes; (void)n_in; (void)out_size;
    const float* hs   = (const float*)d_in[0];
    const float* w_q  = (const float*)d_in[1];
    const float* w_k  = (const float*)d_in[2];
    const float* w_v  = (const float*)d_in[3];
    const float* w_o  = (const float*)d_in[4];
    const float* qw   = (const float*)d_in[5];
    const float* kw   = (const float*)d_in[6];
    const float* cosb = (const float*)d_in[7];
    const float* sinb = (const float*)d_in[8];
    float* out = (float*)d_out;

    float* gqkv;
    __nv_bfloat16 *a0, *a1, *o0, *o1, *wqkv0, *wqkv1, *wo0, *wo1, *k0s, *k1s;
    __half* vt;
    cudaGetSymbolAddress((void**)&gqkv, g_qkv);
    cudaGetSymbolAddress((void**)&a0, g_a0);
    cudaGetSymbolAddress((void**)&a1, g_a1);
    cudaGetSymbolAddress((void**)&o0, g_o0);
    cudaGetSymbolAddress((void**)&o1, g_o1);
    cudaGetSymbolAddress((void**)&wqkv0, g_wqkv0);
    cudaGetSymbolAddress((void**)&wqkv1, g_wqkv1);
    cudaGetSymbolAddress((void**)&wo0, g_wo0);
    cudaGetSymbolAddress((void**)&wo1, g_wo1);
    cudaGetSymbolAddress((void**)&k0s, g_k0s);
    cudaGetSymbolAddress((void**)&k1s, g_k1s);
    cudaGetSymbolAddress((void**)&vt, g_vt);

    cudaFuncSetAttribute(bf16_gemm_kernel, cudaFuncAttributeMaxDynamicSharedMemorySize, GEMM_SMEM);
    cudaFuncSetAttribute(attn_mma_kernel, cudaFuncAttributeMaxDynamicSharedMemorySize, ATTN_SMEM_BYTES);

    // --- pre-pass: hs bf16 splits; weights bf16 splits (transposed, merged) ---
    split_kernel<<<(S_LEN * HDIM / 4 + 255) / 256, 256>>>(hs, a0, a1, S_LEN * HDIM);
    tsplit_kernel<<<dim3(HDIM / 32, HDIM / 32), dim3(32, 8)>>>(
        w_q, wqkv0, wqkv1, HDIM, HDIM);
    tsplit_kernel<<<dim3((NKV * DH) / 32, HDIM / 32), dim3(32, 8)>>>(
        w_k, wqkv0 + (size_t)2048 * HDIM, wqkv1 + (size_t)2048 * HDIM, HDIM, NKV * DH);
    tsplit_kernel<<<dim3((NKV * DH) / 32, HDIM / 32), dim3(32, 8)>>>(
        w_v, wqkv0 + (size_t)2560 * HDIM, wqkv1 + (size_t)2560 * HDIM, HDIM, NKV * DH);
    tsplit_kernel<<<dim3(HDIM / 32, HDIM / 32), dim3(32, 8)>>>(w_o, wo0, wo1, HDIM, HDIM);

    // --- merged QKV projection (bf16x3) ---
    bf16_gemm_kernel<<<dim3(NQKV / 128, S_LEN / 128), 256, GEMM_SMEM>>>(
        a0, a1, wqkv0, wqkv1, gqkv, S_LEN, NQKV, HDIM);

    // --- RMSNorm + RoPE, warp-per-vector, q/k bf16 splits ---
    norm_rope_kernel<<<S_LEN * 12 / 8, 256>>>(
        qw, kw, cosb, sinb, a0, a1, k0s, k1s);

    // --- transpose v to fp16 ---
    vsplit_t_kernel<<<dim3(S_LEN / 32, DH / 32, NKV), dim3(32, 8)>>>(gqkv, vt);

    // --- MMA flash attention (QK bf16x3, PV fp16x1) ---
    attn_mma_kernel<<<dim3(S_LEN / 64, NHQ), 128, ATTN_SMEM_BYTES>>>(
        a0, a1, k0s, k1s, vt, o0, o1);

    // --- O-projection (bf16x3) ---
    bf16_gemm_kernel<<<dim3(HDIM / 128, S_LEN / 128), 256, GEMM_SMEM>>>(
        o0, o1, wo0, wo1, out, S_LEN, HDIM, HDIM);
}